// round 12
// baseline (speedup 1.0000x reference)
#include <cuda_runtime.h>
#include <cstdint>
#include <cstddef>

// ---------------------------------------------------------------------------
#define EMBED    1024
#define HEADS    16
#define HEAD_DIM 64
#define FFN_DIM  4096
#define BSZ      2
#define SUM_LEN  16
#define REG_LEN  2048
#define TOTAL    (SUM_LEN + REG_LEN)   // 2064
#define NCHUNK   16
#define NTOK     (BSZ * TOTAL)         // 4128
#define QKV_STR  3072                  // fused qkv row stride

// tensor-core attention tile constants
#define PADK   144
#define VSTR   148
#define QS_OFF 0
#define KS_OFF 8192
#define VT_OFF 17408
#define ATTN_SMEM ((VT_OFF + 64 * VSTR) * 4)   // 107,520 bytes

// ---------------------------------------------------------------------------
// Static device scratch (no cudaMalloc allowed)
// ---------------------------------------------------------------------------
__device__ __align__(1024) float g_h  [(size_t)NTOK * EMBED];
__device__ __align__(1024) float g_ctx[(size_t)NTOK * EMBED];
__device__ __align__(1024) float g_x1 [(size_t)NTOK * EMBED];
__device__ __align__(1024) float g_h2 [(size_t)NTOK * EMBED];
__device__ __align__(1024) float g_mid[(size_t)NTOK * FFN_DIM];  // qkv, then ffn mid
// tf32-rounded fused qkv weight: [wq;wk;wv] contiguous (3M floats)
__device__ __align__(1024) float g_wr[(size_t)3 * 1024 * 1024];

// ---------------------------------------------------------------------------
// PTX helpers
// ---------------------------------------------------------------------------
__device__ __forceinline__ uint32_t smem_u32(const void* p) {
    uint32_t a;
    asm("{ .reg .u64 t; cvta.to.shared.u64 t, %1; cvt.u32.u64 %0, t; }"
        : "=r"(a) : "l"(p));
    return a;
}
__device__ __forceinline__ float f2tf32(float f) {
    unsigned u;
    asm("cvt.rna.tf32.f32 %0, %1;" : "=r"(u) : "f"(f));
    return __uint_as_float(u);
}
__device__ __forceinline__ float4 cvt4(float4 v) {
    return make_float4(f2tf32(v.x), f2tf32(v.y), f2tf32(v.z), f2tf32(v.w));
}
__device__ __forceinline__ void mma_tf32(float* d, const unsigned* a, const unsigned* b) {
    asm volatile(
        "mma.sync.aligned.m16n8k8.row.col.f32.tf32.tf32.f32 "
        "{%0,%1,%2,%3}, {%4,%5,%6,%7}, {%8,%9}, {%0,%1,%2,%3};"
        : "+f"(d[0]), "+f"(d[1]), "+f"(d[2]), "+f"(d[3])
        : "r"(a[0]), "r"(a[1]), "r"(a[2]), "r"(a[3]), "r"(b[0]), "r"(b[1]));
}
__device__ __forceinline__ void ldsm_x4(unsigned* r, uint32_t addr) {
    asm volatile("ldmatrix.sync.aligned.m8n8.x4.shared.b16 {%0,%1,%2,%3}, [%4];"
                 : "=r"(r[0]), "=r"(r[1]), "=r"(r[2]), "=r"(r[3]) : "r"(addr));
}
#define CP_ASYNC16(dst, src, sz) \
    asm volatile("cp.async.cg.shared.global [%0], [%1], 16, %2;" \
                 :: "r"(dst), "l"(src), "r"(sz) : "memory")
#define CP_COMMIT() asm volatile("cp.async.commit_group;" ::: "memory")
#define CP_WAIT2()  asm volatile("cp.async.wait_group 2;" ::: "memory")
#define CP_WAIT0()  asm volatile("cp.async.wait_group 0;" ::: "memory")

// ---------------------------------------------------------------------------
// TF32 tensor-core GEMM (NT), 256x128 tile, BK=16, 256 threads (8 warps 4x2).
// Each warp: 64 (M) x 64 (N). cp.async 4-stage, one barrier per k-iter.
// Optional folded second problem (M=SUM_LEN) on last y-block.
// ---------------------------------------------------------------------------
#define STAGES 4
#define STAGE_BYTES 24576              // A 16KB (256 rows) + B 8KB (128 rows)
#define GEMM_SMEM (STAGES * STAGE_BYTES)

template<bool RELU, bool HAS_BIAS, bool HAS_RESID, bool ROUND_OUT, bool FOLD>
__global__ __launch_bounds__(256) void gemm_tc(
    const float* __restrict__ A, const float* __restrict__ B,
    float* __restrict__ C, int M, int NC, int K,
    const float* __restrict__ bias, const float* __restrict__ resid,
    size_t zA, size_t zC, size_t zR,
    const float* A2, const float* B2, const float* bias2,
    const float* resid2, float* C2)
{
    extern __shared__ char smraw[];
    const uint32_t smb = smem_u32(smraw);

    const bool sumblk = FOLD && (blockIdx.y == gridDim.y - 1);
    if (sumblk) { A = A2; B = B2; bias = bias2; resid = resid2; C = C2; M = SUM_LEN; }
    const int by = sumblk ? 0 : blockIdx.y;

    A += (size_t)blockIdx.z * zA;
    C += (size_t)blockIdx.z * zC;
    if (HAS_RESID) resid += (size_t)blockIdx.z * zR;

    const int tid  = threadIdx.x;
    const int lane = tid & 31;
    const int warp = tid >> 5;
    const int wm   = (warp >> 1) * 64;   // warp row origin: 0/64/128/192
    const int wn   = (warp & 1) * 64;

    // staging: thread owns A rows srow, srow+128 and B row srow; k-chunks scol, scol+1
    const int srow = tid >> 1;
    const int scol = (tid & 1) * 2;
    const int rowA0 = by * 256 + srow;
    const int rowA1 = rowA0 + 128;
    const int rowB  = blockIdx.x * 128 + srow;
    const uint32_t asz0 = (rowA0 < M) ? 16u : 0u;
    const uint32_t asz1 = (rowA1 < M) ? 16u : 0u;
    const float* Ag0 = A + (size_t)(rowA0 < M ? rowA0 : 0) * K + scol * 4;
    const float* Ag1 = A + (size_t)(rowA1 < M ? rowA1 : 0) * K + scol * 4;
    const float* Bg  = B + (size_t)rowB * K + scol * 4;
    const uint32_t ssw  = (srow >> 1) & 3;   // same phase for srow+128 (128/2 % 4 == 0)
    const uint32_t c0 = ((uint32_t)scol ^ ssw) << 4;
    const uint32_t c1 = (((uint32_t)scol + 1) ^ ssw) << 4;
    const uint32_t dA0 = srow * 64;
    const uint32_t dA1 = (srow + 128) * 64;
    const uint32_t dB  = 16384 + srow * 64;

    // ldmatrix lane addressing: 4 A m16-tiles per warp, 4 B n16-pairs
    const int arow0 = wm + (lane & 15);
    uint32_t aoff[4], asks[4];
#pragma unroll
    for (int mt = 0; mt < 4; mt++) {
        int r = arow0 + 16 * mt;
        aoff[mt] = r * 64;
        asks[mt] = (r >> 1) & 3;
    }
    const uint32_t acb = lane >> 4;
    const int bn = wn + ((lane >> 4) << 3) + (lane & 7);
    const uint32_t bcb = (lane >> 3) & 1;
    uint32_t boff[4], bsk[4];
#pragma unroll
    for (int p = 0; p < 4; p++) {
        int n = bn + p * 16;
        boff[p] = 16384 + n * 64;
        bsk[p]  = (n >> 1) & 3;
    }

    float acc[4][8][4];
#pragma unroll
    for (int mt = 0; mt < 4; mt++)
#pragma unroll
        for (int nt = 0; nt < 8; nt++)
#pragma unroll
            for (int i = 0; i < 4; i++) acc[mt][nt][i] = 0.f;

    const int nstep = K >> 4;

#pragma unroll
    for (int s = 0; s < STAGES - 1; s++) {
        uint32_t ab = smb + s * STAGE_BYTES;
        const float* ag0 = Ag0 + s * 16;
        const float* ag1 = Ag1 + s * 16;
        const float* bg  = Bg  + s * 16;
        CP_ASYNC16(ab + dA0 + c0, ag0,     asz0);
        CP_ASYNC16(ab + dA0 + c1, ag0 + 4, asz0);
        CP_ASYNC16(ab + dA1 + c0, ag1,     asz1);
        CP_ASYNC16(ab + dA1 + c1, ag1 + 4, asz1);
        CP_ASYNC16(ab + dB  + c0, bg,      16u);
        CP_ASYNC16(ab + dB  + c1, bg + 4,  16u);
        CP_COMMIT();
    }

    for (int i = 0; i < nstep; i++) {
        CP_WAIT2();
        __syncthreads();

        const int nf = i + STAGES - 1;
        if (nf < nstep) {
            uint32_t ab = smb + (nf % STAGES) * STAGE_BYTES;
            const float* ag0 = Ag0 + nf * 16;
            const float* ag1 = Ag1 + nf * 16;
            const float* bg  = Bg  + nf * 16;
            CP_ASYNC16(ab + dA0 + c0, ag0,     asz0);
            CP_ASYNC16(ab + dA0 + c1, ag0 + 4, asz0);
            CP_ASYNC16(ab + dA1 + c0, ag1,     asz1);
            CP_ASYNC16(ab + dA1 + c1, ag1 + 4, asz1);
            CP_ASYNC16(ab + dB  + c0, bg,      16u);
            CP_ASYNC16(ab + dB  + c1, bg + 4,  16u);
        }
        CP_COMMIT();

        const uint32_t ab = smb + (i % STAGES) * STAGE_BYTES;

#pragma unroll
        for (int sub = 0; sub < 2; sub++) {
            const uint32_t ch  = sub * 2 + acb;
            const uint32_t chb = sub * 2 + bcb;
            unsigned a[4][4];
#pragma unroll
            for (int mt = 0; mt < 4; mt++)
                ldsm_x4(a[mt], ab + aoff[mt] + ((ch ^ asks[mt]) << 4));
#pragma unroll
            for (int p = 0; p < 4; p++) {
                unsigned bf[4];
                ldsm_x4(bf, ab + boff[p] + ((chb ^ bsk[p]) << 4));
#pragma unroll
                for (int mt = 0; mt < 4; mt++) {
                    mma_tf32(acc[mt][2 * p    ], a[mt], &bf[0]);
                    mma_tf32(acc[mt][2 * p + 1], a[mt], &bf[2]);
                }
            }
        }
    }

    const int fr = lane >> 2, fk = lane & 3;
    const int rowbase = by * 256 + wm + fr;
    const int colbase = blockIdx.x * 128 + wn + fk * 2;
#pragma unroll
    for (int mt = 0; mt < 4; mt++) {
#pragma unroll
        for (int half = 0; half < 2; half++) {
            int r = rowbase + mt * 16 + half * 8;
            if (r >= M) continue;
#pragma unroll
            for (int nt = 0; nt < 8; nt++) {
                int cidx = colbase + nt * 8;
                float v0 = acc[mt][nt][half * 2 + 0];
                float v1 = acc[mt][nt][half * 2 + 1];
                if (HAS_BIAS) { v0 += bias[cidx]; v1 += bias[cidx + 1]; }
                if (RELU) { v0 = fmaxf(v0, 0.f); v1 = fmaxf(v1, 0.f); }
                if (HAS_RESID) {
                    float2 rr = *(const float2*)(resid + (size_t)r * NC + cidx);
                    v0 += rr.x; v1 += rr.y;
                }
                if (ROUND_OUT) { v0 = f2tf32(v0); v1 = f2tf32(v1); }
                *(float2*)(C + (size_t)r * NC + cidx) = make_float2(v0, v1);
            }
        }
    }
}

// ---------------------------------------------------------------------------
// Round only the fused QKV weight concat (wq|wk|wv) to tf32-rna
// ---------------------------------------------------------------------------
struct RoundSrcs3 { const float4* s[3]; };

__global__ __launch_bounds__(256) void round_qkv_kernel(
    RoundSrcs3 srcs, float4* __restrict__ dst)
{
    size_t i = (size_t)blockIdx.x * 256 + threadIdx.x;   // < 786432
    int r = (int)(i >> 18);
    dst[i] = cvt4(srcs.s[r][i - ((size_t)r << 18)]);
}

// ---------------------------------------------------------------------------
// LayerNorm (output rounded to tf32)
// ---------------------------------------------------------------------------
__global__ __launch_bounds__(256) void ln_kernel(
    const float* __restrict__ x,
    const float* __restrict__ gs, const float* __restrict__ bs,
    const float* __restrict__ gr, const float* __restrict__ br,
    float* __restrict__ out)
{
    int row = blockIdx.x;
    int t = row % TOTAL;
    const float* g = (t < SUM_LEN) ? gs : gr;
    const float* b = (t < SUM_LEN) ? bs : br;
    int tid = threadIdx.x;
    int lane = tid & 31, warp = tid >> 5;

    float4 v = ((const float4*)(x + (size_t)row * EMBED))[tid];
    float s = v.x + v.y + v.z + v.w;
    float q = v.x * v.x + v.y * v.y + v.z * v.z + v.w * v.w;

    __shared__ float rs_[8], rq_[8];
#pragma unroll
    for (int o = 16; o; o >>= 1) {
        s += __shfl_xor_sync(0xffffffffu, s, o);
        q += __shfl_xor_sync(0xffffffffu, q, o);
    }
    if (lane == 0) { rs_[warp] = s; rq_[warp] = q; }
    __syncthreads();
    if (tid < 32) {
        s = (lane < 8) ? rs_[lane] : 0.f;
        q = (lane < 8) ? rq_[lane] : 0.f;
#pragma unroll
        for (int o = 4; o; o >>= 1) {
            s += __shfl_xor_sync(0xffffffffu, s, o);
            q += __shfl_xor_sync(0xffffffffu, q, o);
        }
        if (lane == 0) { rs_[0] = s; rq_[0] = q; }
    }
    __syncthreads();

    float mean = rs_[0] * (1.f / EMBED);
    float var  = rq_[0] * (1.f / EMBED) - mean * mean;
    float rinv = rsqrtf(var + 1e-5f);

    float4 gg = ((const float4*)g)[tid];
    float4 bb = ((const float4*)b)[tid];
    float4 o4;
    o4.x = (v.x - mean) * rinv * gg.x + bb.x;
    o4.y = (v.y - mean) * rinv * gg.y + bb.y;
    o4.z = (v.z - mean) * rinv * gg.z + bb.z;
    o4.w = (v.w - mean) * rinv * gg.w + bb.w;
    ((float4*)(out + (size_t)row * EMBED))[tid] = cvt4(o4);
}

// ---------------------------------------------------------------------------
// TENSOR-CORE attention for REG queries. Grid (NCHUNK, HEADS, BSZ), 256 thr.
// Q/K staged RAW via cp.async (MMA truncates); scale 0.125 applied post-MMA.
// ---------------------------------------------------------------------------
__global__ __launch_bounds__(256) void attn_reg_kernel(
    const float* __restrict__ QKV, const int* __restrict__ ranges,
    float* __restrict__ CTX)
{
    extern __shared__ float sm[];
    const uint32_t smb = smem_u32(sm);
    const uint32_t QS = smb + QS_OFF * 4;
    const uint32_t KS = smb + KS_OFF * 4;
    const uint32_t VT = smb + VT_OFF * 4;

    const int c = blockIdx.x, h = blockIdx.y, b = blockIdx.z;
    const int start = ranges[(b * NCHUNK + c) * 2];
    const int next  = (c + 1 < NCHUNK) ? ranges[(b * NCHUNK + c + 1) * 2] : REG_LEN;
    const int width = next - start;
    const int nsum  = c;
    const int nk    = nsum + width;
    const size_t bb = (size_t)b * TOTAL;

    const int tid = threadIdx.x;

    for (int idx = tid; idx < 128 * 16; idx += 256) {
        int row = idx >> 4, ch = idx & 15;
        int tok = SUM_LEN + start + row;
        const float* src = QKV + (bb + tok) * QKV_STR + h * HEAD_DIM + ch * 4;
        CP_ASYNC16(QS + row * 256 + (((uint32_t)ch ^ (uint32_t)(row & 15)) << 4),
                   src, 16u);
    }
    for (int idx = tid; idx < PADK * 16; idx += 256) {
        int j = idx >> 4, ch = idx & 15;
        uint32_t sz = (j < nk) ? 16u : 0u;
        int tok = (j < nsum) ? j : (j < nk ? SUM_LEN + start + (j - nsum) : 0);
        const float* src = QKV + (bb + tok) * QKV_STR + h * HEAD_DIM + 1024 + ch * 4;
        CP_ASYNC16(KS + j * 256 + (((uint32_t)ch ^ (uint32_t)(j & 15)) << 4),
                   src, sz);
    }
    CP_COMMIT();

    for (int idx = tid; idx < PADK * 16; idx += 256) {
        int j = idx >> 4, ch = idx & 15;
        float4 t4 = make_float4(0.f, 0.f, 0.f, 0.f);
        if (j < nk) {
            int tok = (j < nsum) ? j : (SUM_LEN + start + (j - nsum));
            t4 = *(const float4*)(QKV + (bb + tok) * QKV_STR + h * HEAD_DIM
                                  + 2048 + ch * 4);
        }
        int d = ch * 4;
        sm[VT_OFF + (d + 0) * VSTR + j] = t4.x;
        sm[VT_OFF + (d + 1) * VSTR + j] = t4.y;
        sm[VT_OFF + (d + 2) * VSTR + j] = t4.z;
        sm[VT_OFF + (d + 3) * VSTR + j] = t4.w;
    }
    CP_WAIT0();
    __syncthreads();

    const int lane = tid & 31, wid = tid >> 5;
    const int fr = lane >> 2, fk = lane & 3;

    float S[18][4];
#pragma unroll
    for (int t = 0; t < 18; t++)
#pragma unroll
        for (int i = 0; i < 4; i++) S[t][i] = 0.f;

    {
        const int arow = wid * 16 + (lane & 15);
        const uint32_t abase = QS + (arow * 64) * 4;
        const uint32_t asw   = (arow & 15);
        const int krow = ((lane >> 4) << 3) + (lane & 7);
        const uint32_t kcb = (lane >> 3) & 1;
#pragma unroll
        for (int k8 = 0; k8 < 8; k8++) {
            unsigned a[4];
            uint32_t ach = 2 * k8 + (lane >> 4);
            ldsm_x4(a, abase + ((ach ^ asw) << 4));
            uint32_t bch = 2 * k8 + kcb;
#pragma unroll
            for (int p = 0; p < 9; p++) {
                unsigned bf[4];
                int kr = 16 * p + krow;
                ldsm_x4(bf, KS + (kr * 64) * 4 + ((bch ^ (uint32_t)(kr & 15)) << 4));
                mma_tf32(S[2 * p],     a, &bf[0]);
                mma_tf32(S[2 * p + 1], a, &bf[2]);
            }
        }
    }

    const int q0 = wid * 16 + fr;
    const int lim0 = nsum + q0, lim1 = lim0 + 8;
    float m0 = -1e30f, m1 = -1e30f;
#pragma unroll
    for (int t = 0; t < 18; t++) {
        int cb = 8 * t + 2 * fk;
        S[t][0] = (cb     <= lim0) ? S[t][0] * 0.125f : -1e30f;
        S[t][1] = (cb + 1 <= lim0) ? S[t][1] * 0.125f : -1e30f;
        S[t][2] = (cb     <= lim1) ? S[t][2] * 0.125f : -1e30f;
        S[t][3] = (cb + 1 <= lim1) ? S[t][3] * 0.125f : -1e30f;
        m0 = fmaxf(m0, fmaxf(S[t][0], S[t][1]));
        m1 = fmaxf(m1, fmaxf(S[t][2], S[t][3]));
    }
    m0 = fmaxf(m0, __shfl_xor_sync(0xffffffffu, m0, 1));
    m0 = fmaxf(m0, __shfl_xor_sync(0xffffffffu, m0, 2));
    m1 = fmaxf(m1, __shfl_xor_sync(0xffffffffu, m1, 1));
    m1 = fmaxf(m1, __shfl_xor_sync(0xffffffffu, m1, 2));

    float l0 = 0.f, l1 = 0.f;
#pragma unroll
    for (int t = 0; t < 18; t++) {
        S[t][0] = f2tf32(__expf(S[t][0] - m0));
        S[t][1] = f2tf32(__expf(S[t][1] - m0));
        S[t][2] = f2tf32(__expf(S[t][2] - m1));
        S[t][3] = f2tf32(__expf(S[t][3] - m1));
        l0 += S[t][0] + S[t][1];
        l1 += S[t][2] + S[t][3];
    }
    l0 += __shfl_xor_sync(0xffffffffu, l0, 1);
    l0 += __shfl_xor_sync(0xffffffffu, l0, 2);
    l1 += __shfl_xor_sync(0xffffffffu, l1, 1);
    l1 += __shfl_xor_sync(0xffffffffu, l1, 2);

    float O[8][4];
#pragma unroll
    for (int nt = 0; nt < 8; nt++)
#pragma unroll
        for (int i = 0; i < 4; i++) O[nt][i] = 0.f;

    const int s0 = (lane & ~3) | (fk >> 1);
    const int s1 = s0 + 2;
    const bool e = fk & 1;
    const int vrow0 = ((lane >> 4) << 3) + (lane & 7);
    const uint32_t vcb = (lane >> 3) & 1;

#pragma unroll
    for (int t = 0; t < 18; t++) {
        float x0 = __shfl_sync(0xffffffffu, S[t][0], s0);
        float x1 = __shfl_sync(0xffffffffu, S[t][1], s0);
        float x2 = __shfl_sync(0xffffffffu, S[t][2], s0);
        float x3 = __shfl_sync(0xffffffffu, S[t][3], s0);
        float y0 = __shfl_sync(0xffffffffu, S[t][0], s1);
        float y1 = __shfl_sync(0xffffffffu, S[t][1], s1);
        float y2 = __shfl_sync(0xffffffffu, S[t][2], s1);
        float y3 = __shfl_sync(0xffffffffu, S[t][3], s1);
        unsigned a[4];
        a[0] = __float_as_uint(e ? x1 : x0);
        a[1] = __float_as_uint(e ? x3 : x2);
        a[2] = __float_as_uint(e ? y1 : y0);
        a[3] = __float_as_uint(e ? y3 : y2);
        const uint32_t vch = (2 * t + vcb) << 4;
#pragma unroll
        for (int pn = 0; pn < 4; pn++) {
            unsigned bf[4];
            int vr = 16 * pn + vrow0;
            ldsm_x4(bf, VT + (vr * VSTR) * 4 + vch);
            mma_tf32(O[2 * pn],     a, &bf[0]);
            mma_tf32(O[2 * pn + 1], a, &bf[2]);
        }
    }

    const float inv0 = 1.f / l0, inv1 = 1.f / l1;
    if (q0 < width) {
        int tok = SUM_LEN + start + q0;
        float* op = CTX + (bb + tok) * EMBED + h * HEAD_DIM + 2 * fk;
#pragma unroll
        for (int nt = 0; nt < 8; nt++)
            *(float2*)(op + 8 * nt) =
                make_float2(f2tf32(O[nt][0] * inv0), f2tf32(O[nt][1] * inv0));
    }
    if (q0 + 8 < width) {
        int tok = SUM_LEN + start + q0 + 8;
        float* op = CTX + (bb + tok) * EMBED + h * HEAD_DIM + 2 * fk;
#pragma unroll
        for (int nt = 0; nt < 8; nt++)
            *(float2*)(op + 8 * nt) =
                make_float2(f2tf32(O[nt][2] * inv1), f2tf32(O[nt][3] * inv1));
    }
}

// ---------------------------------------------------------------------------
// Attention, SUM queries. One warp per (b, h, s); qkv fused buffer.
// ---------------------------------------------------------------------------
__global__ __launch_bounds__(256) void attn_sum_kernel(
    const float* __restrict__ QKV, const int* __restrict__ ranges,
    float* __restrict__ CTX)
{
    int gw = (blockIdx.x * blockDim.x + threadIdx.x) >> 5;
    int lane = threadIdx.x & 31;
    if (gw >= BSZ * HEADS * SUM_LEN) return;
    int b = gw / (HEADS * SUM_LEN);
    int rem = gw % (HEADS * SUM_LEN);
    int h = rem / SUM_LEN;
    int s = rem % SUM_LEN;

    int start = ranges[(b * NCHUNK + s) * 2];
    int next  = (s + 1 < NCHUNK) ? ranges[(b * NCHUNK + s + 1) * 2] : REG_LEN;

    size_t bbase = (size_t)b * TOTAL;
    float2 q2 = ((const float2*)(QKV + (bbase + s) * QKV_STR + h * HEAD_DIM))[lane];
    q2.x *= 0.125f; q2.y *= 0.125f;

    float m = -1e30f, l = 0.f, cx = 0.f, cy = 0.f;

#define ASTEP(tok_expr)                                                                 \
    do {                                                                                \
        int tok = (tok_expr);                                                           \
        size_t ko = (bbase + tok) * QKV_STR + h * HEAD_DIM;                             \
        float2 kk = ((const float2*)(QKV + ko + 1024))[lane];                           \
        float part = q2.x * kk.x + q2.y * kk.y;                                         \
        _Pragma("unroll")                                                               \
        for (int o = 16; o; o >>= 1) part += __shfl_xor_sync(0xffffffffu, part, o);     \
        float mn = fmaxf(m, part);                                                      \
        float alpha = __expf(m - mn);                                                   \
        float p = __expf(part - mn);                                                    \
        l = l * alpha + p;                                                              \
        float2 vv = ((const float2*)(QKV + ko + 2048))[lane];                           \
        cx = fmaf(p, vv.x, cx * alpha);                                                 \
        cy = fmaf(p, vv.y, cy * alpha);                                                 \
        m = mn;                                                                         \
    } while (0)

    for (int t = 0; t <= s; t++)       ASTEP(t);
    for (int t = start; t < next; t++) ASTEP(SUM_LEN + t);
#undef ASTEP

    float inv = 1.f / l;
    ((float2*)(CTX + (bbase + s) * EMBED + h * HEAD_DIM))[lane] =
        make_float2(f2tf32(cx * inv), f2tf32(cy * inv));
}

// ---------------------------------------------------------------------------
// Launch sequence
// ---------------------------------------------------------------------------
extern "C" void kernel_launch(void* const* d_in, const int* in_sizes, int n_in,
                              void* d_out, int out_size)
{
    const float* x      = (const float*)d_in[0];
    const float* w_q    = (const float*)d_in[1];
    const float* w_k    = (const float*)d_in[2];
    const float* w_v    = (const float*)d_in[3];
    const float* w_o    = (const float*)d_in[4];
    const float* ln1_sg = (const float*)d_in[5];
    const float* ln1_sb = (const float*)d_in[6];
    const float* ln1_rg = (const float*)d_in[7];
    const float* ln1_rb = (const float*)d_in[8];
    const float* sfc1w  = (const float*)d_in[9];
    const float* sfc1b  = (const float*)d_in[10];
    const float* sfc2w  = (const float*)d_in[11];
    const float* sfc2b  = (const float*)d_in[12];
    const float* rfc1w  = (const float*)d_in[13];
    const float* rfc1b  = (const float*)d_in[14];
    const float* rfc2w  = (const float*)d_in[15];
    const float* rfc2b  = (const float*)d_in[16];
    const float* ln2_sg = (const float*)d_in[17];
    const float* ln2_sb = (const float*)d_in[18];
    const float* ln2_rg = (const float*)d_in[19];
    const float* ln2_rb = (const float*)d_in[20];
    const int*   ranges = (const int*)d_in[21];
    float* out = (float*)d_out;

    void *ph, *pctx, *px1, *ph2, *pmid, *pwr;
    cudaGetSymbolAddress(&ph,   g_h);
    cudaGetSymbolAddress(&pctx, g_ctx);
    cudaGetSymbolAddress(&px1,  g_x1);
    cudaGetSymbolAddress(&ph2,  g_h2);
    cudaGetSymbolAddress(&pmid, g_mid);
    cudaGetSymbolAddress(&pwr,  g_wr);
    float* h   = (float*)ph;
    float* ctx = (float*)pctx;
    float* x1  = (float*)px1;
    float* h2  = (float*)ph2;
    float* mid = (float*)pmid;
    float* wr  = (float*)pwr;

    const size_t zE = (size_t)TOTAL * EMBED;
    const size_t zF = (size_t)TOTAL * FFN_DIM;

    cudaFuncSetAttribute(attn_reg_kernel,
                         cudaFuncAttributeMaxDynamicSharedMemorySize, ATTN_SMEM);
    cudaFuncSetAttribute(attn_reg_kernel,
                         cudaFuncAttributePreferredSharedMemoryCarveout, 100);
    cudaFuncSetAttribute(gemm_tc<false, false, false, false, false>,
                         cudaFuncAttributeMaxDynamicSharedMemorySize, GEMM_SMEM);
    cudaFuncSetAttribute(gemm_tc<false, false, false, false, false>,
                         cudaFuncAttributePreferredSharedMemoryCarveout, 100);
    cudaFuncSetAttribute(gemm_tc<false, false, true, false, false>,
                         cudaFuncAttributeMaxDynamicSharedMemorySize, GEMM_SMEM);
    cudaFuncSetAttribute(gemm_tc<false, false, true, false, false>,
                         cudaFuncAttributePreferredSharedMemoryCarveout, 100);
    cudaFuncSetAttribute(gemm_tc<true, true, false, true, true>,
                         cudaFuncAttributeMaxDynamicSharedMemorySize, GEMM_SMEM);
    cudaFuncSetAttribute(gemm_tc<true, true, false, true, true>,
                         cudaFuncAttributePreferredSharedMemoryCarveout, 100);
    cudaFuncSetAttribute(gemm_tc<false, true, true, false, true>,
                         cudaFuncAttributeMaxDynamicSharedMemorySize, GEMM_SMEM);
    cudaFuncSetAttribute(gemm_tc<false, true, true, false, true>,
                         cudaFuncAttributePreferredSharedMemoryCarveout, 100);

    // 0) Round the fused qkv weight concat to tf32 (rna)
    {
        RoundSrcs3 rs;
        rs.s[0] = (const float4*)w_q;
        rs.s[1] = (const float4*)w_k;
        rs.s[2] = (const float4*)w_v;
        round_qkv_kernel<<<3072, 256>>>(rs, (float4*)wr);
    }

    // 1) LN1
    ln_kernel<<<NTOK, 256>>>(x, ln1_sg, ln1_sb, ln1_rg, ln1_rb, h);

    // 2) Fused QKV projection -> mid [NTOK, 3072]   (M=4128 -> 17 y-blocks of 256)
    gemm_tc<false, false, false, false, false><<<dim3(24, 17, 1), 256, GEMM_SMEM>>>(
        h, wr, mid, NTOK, QKV_STR, EMBED, nullptr, nullptr, 0, 0, 0,
        nullptr, nullptr, nullptr, nullptr, nullptr);

    // 3) Sparse masked attention
    attn_reg_kernel<<<dim3(NCHUNK, HEADS, BSZ), 256, ATTN_SMEM>>>(mid, ranges, ctx);
    attn_sum_kernel<<<(BSZ * HEADS * SUM_LEN) / 8, 256>>>(mid, ranges, ctx);

    // 4) Output projection + residual: x1 = x + ctx @ Wo^T
    gemm_tc<false, false, true, false, false><<<dim3(8, 17, 1), 256, GEMM_SMEM>>>(
        ctx, w_o, x1, NTOK, EMBED, EMBED, nullptr, x, 0, 0, 0,
        nullptr, nullptr, nullptr, nullptr, nullptr);

    // 5) LN2
    ln_kernel<<<NTOK, 256>>>(x1, ln2_sg, ln2_sb, ln2_rg, ln2_rb, h2);

    // 6) FFN — reg segments (8 y-blocks of 256) + folded sum block (y=8)
    gemm_tc<true, true, false, true, true><<<dim3(32, 9, BSZ), 256, GEMM_SMEM>>>(
        h2 + (size_t)SUM_LEN * EMBED, rfc1w, mid + (size_t)SUM_LEN * FFN_DIM,
        REG_LEN, FFN_DIM, EMBED, rfc1b, nullptr, zE, zF, 0,
        h2, sfc1w, sfc1b, nullptr, mid);
    gemm_tc<false, true, true, false, true><<<dim3(8, 9, BSZ), 256, GEMM_SMEM>>>(
        mid + (size_t)SUM_LEN * FFN_DIM, rfc2w, out + (size_t)SUM_LEN * EMBED,
        REG_LEN, EMBED, FFN_DIM, rfc2b, x1 + (size_t)SUM_LEN * EMBED, zF, zE, zE,
        mid, sfc2w, sfc2b, x1, out);
}